// round 16
// baseline (speedup 1.0000x reference)
#include <cuda_runtime.h>
#include <cuda_bf16.h>
#include <math.h>
#include <stdint.h>

#define BATCH 512
#define HW 36
#define NPIX 1296
#define NOSC 1296
#define KCON 8
#define STEPS 25

#define FC_M 6144
#define FC_K 3456
#define FC_N 864

#define PHASE_SLICE (BATCH*NOSC)
#define PHASE_TOTAL ((STEPS+1)*PHASE_SLICE)

// ---------------- scratch ----------------
__device__ float g_c1[BATCH*8*NPIX];
__device__ float g_c2[BATCH*16*NPIX];
__device__ __nv_bfloat16 g_ah[(size_t)FC_M*FC_K];
__device__ __nv_bfloat16 g_al[(size_t)FC_M*FC_K];
__device__ __nv_bfloat16 g_wh[(size_t)FC_N*FC_K];
__device__ __nv_bfloat16 g_wl[(size_t)FC_N*FC_K];

__device__ __forceinline__ uint32_t smem_u32(const void* p) {
    uint32_t a;
    asm("{ .reg .u64 t; cvta.to.shared.u64 t, %1; cvt.u32.u64 %0, t; }"
        : "=r"(a) : "l"(p));
    return a;
}
#define LDS32(v, addr) \
    asm volatile("ld.shared.b32 %0, [%1];" : "=r"(v) : "r"(addr))
#define MMA16816(d, a0,a1,a2,a3, b0,b1) \
    asm volatile("mma.sync.aligned.m16n8k16.row.col.f32.bf16.bf16.f32 " \
        "{%0,%1,%2,%3}, {%4,%5,%6,%7}, {%8,%9}, {%0,%1,%2,%3};" \
        : "+f"((d)[0]),"+f"((d)[1]),"+f"((d)[2]),"+f"((d)[3]) \
        : "r"(a0),"r"(a1),"r"(a2),"r"(a3),"r"(b0),"r"(b1))

// ---------------- conv1: 1 -> 8, relu ----------------
__global__ void conv1_kernel(const float* __restrict__ in,
                             const float* __restrict__ w,
                             const float* __restrict__ bias) {
    __shared__ float s[NPIX];
    int b = blockIdx.x;
    for (int i = threadIdx.x; i < NPIX; i += blockDim.x) s[i] = in[b*NPIX + i];
    __syncthreads();
    for (int idx = threadIdx.x; idx < 8*NPIX; idx += blockDim.x) {
        int oc = idx / NPIX, p = idx - oc*NPIX;
        int h = p / HW, x = p - h*HW;
        float acc = bias[oc];
        #pragma unroll
        for (int kh = 0; kh < 3; kh++) {
            int ih = h + kh - 1;
            if ((unsigned)ih >= HW) continue;
            #pragma unroll
            for (int kw = 0; kw < 3; kw++) {
                int iw = x + kw - 1;
                if ((unsigned)iw >= HW) continue;
                acc += s[ih*HW + iw] * w[oc*9 + kh*3 + kw];
            }
        }
        g_c1[b*8*NPIX + idx] = fmaxf(acc, 0.f);
    }
}

// ---------------- conv2: 8 -> 16, relu; 2-pixel tiling (R11 config) -------
__global__ void __launch_bounds__(512)
conv2_kernel(const float* __restrict__ w,
             const float* __restrict__ bias) {
    __shared__ float s[8*NPIX];
    __shared__ float ws[8*9*16];     // [ic][k][oc]
    __shared__ float bs[16];
    int b = blockIdx.x;
    for (int i = threadIdx.x; i < 8*NPIX; i += blockDim.x) s[i] = g_c1[b*8*NPIX + i];
    for (int i = threadIdx.x; i < 16*8*9; i += blockDim.x) {
        int oc = i / 72, r = i - oc*72;
        ws[r*16 + oc] = w[i];
    }
    if (threadIdx.x < 16) bs[threadIdx.x] = bias[threadIdx.x];
    __syncthreads();
    for (int t = threadIdx.x; t < NPIX/2; t += blockDim.x) {
        int p0 = 2*t;
        int h = p0 / HW, x0 = p0 - h*HW;
        float acc0[16], acc1[16];
        #pragma unroll
        for (int oc = 0; oc < 16; oc++) { acc0[oc] = bs[oc]; acc1[oc] = bs[oc]; }
        for (int ic = 0; ic < 8; ic++) {
            float v[3][4];
            #pragma unroll
            for (int kh = 0; kh < 3; kh++) {
                int r = h + kh - 1;
                bool rok = (unsigned)r < HW;
                #pragma unroll
                for (int j = 0; j < 4; j++) {
                    int c = x0 + j - 1;
                    v[kh][j] = (rok && (unsigned)c < HW) ? s[ic*NPIX + r*HW + c] : 0.f;
                }
            }
            #pragma unroll
            for (int kh = 0; kh < 3; kh++)
                #pragma unroll
                for (int kw = 0; kw < 3; kw++) {
                    float a0 = v[kh][kw], a1 = v[kh][kw+1];
                    const float4* wp = (const float4*)&ws[((ic*3+kh)*3+kw)*16];
                    #pragma unroll
                    for (int j = 0; j < 4; j++) {
                        float4 w4 = wp[j];
                        acc0[4*j+0] += a0*w4.x; acc0[4*j+1] += a0*w4.y;
                        acc0[4*j+2] += a0*w4.z; acc0[4*j+3] += a0*w4.w;
                        acc1[4*j+0] += a1*w4.x; acc1[4*j+1] += a1*w4.y;
                        acc1[4*j+2] += a1*w4.z; acc1[4*j+3] += a1*w4.w;
                    }
                }
        }
        #pragma unroll
        for (int oc = 0; oc < 16; oc++) {
            float2 o = make_float2(fmaxf(acc0[oc], 0.f), fmaxf(acc1[oc], 0.f));
            *(float2*)&g_c2[(size_t)b*16*NPIX + (size_t)oc*NPIX + p0] = o;
        }
    }
}

// ---------------- conv3: 16 -> 32, sigmoid; 2-pixel tiling (R11 config) ---
__global__ void __launch_bounds__(512)
conv3_kernel(const float* __restrict__ w,
             const float* __restrict__ bias) {
    extern __shared__ float dyn[];
    float* s  = dyn;                  // 16*NPIX
    float* ws = dyn + 16*NPIX;        // [ic][k][oc] 16*9*32
    float* bs = ws + 16*9*32;         // 32
    int b = blockIdx.x;
    for (int i = threadIdx.x; i < 16*NPIX; i += blockDim.x) s[i] = g_c2[b*16*NPIX + i];
    for (int i = threadIdx.x; i < 32*16*9; i += blockDim.x) {
        int oc = i / 144, r = i - oc*144;
        ws[r*32 + oc] = w[i];
    }
    if (threadIdx.x < 32) bs[threadIdx.x] = bias[threadIdx.x];
    __syncthreads();
    for (int t = threadIdx.x; t < NPIX/2; t += blockDim.x) {
        int p0 = 2*t;
        int h = p0 / HW, x0 = p0 - h*HW;
        float acc0[32], acc1[32];
        #pragma unroll
        for (int oc = 0; oc < 32; oc++) { acc0[oc] = bs[oc]; acc1[oc] = bs[oc]; }
        for (int ic = 0; ic < 16; ic++) {
            float v[3][4];
            #pragma unroll
            for (int kh = 0; kh < 3; kh++) {
                int r = h + kh - 1;
                bool rok = (unsigned)r < HW;
                #pragma unroll
                for (int j = 0; j < 4; j++) {
                    int c = x0 + j - 1;
                    v[kh][j] = (rok && (unsigned)c < HW) ? s[ic*NPIX + r*HW + c] : 0.f;
                }
            }
            #pragma unroll
            for (int kh = 0; kh < 3; kh++)
                #pragma unroll
                for (int kw = 0; kw < 3; kw++) {
                    float a0 = v[kh][kw], a1 = v[kh][kw+1];
                    const float4* wp = (const float4*)&ws[((ic*3+kh)*3+kw)*32];
                    #pragma unroll
                    for (int j = 0; j < 8; j++) {
                        float4 w4 = wp[j];
                        acc0[4*j+0] += a0*w4.x; acc0[4*j+1] += a0*w4.y;
                        acc0[4*j+2] += a0*w4.z; acc0[4*j+3] += a0*w4.w;
                        acc1[4*j+0] += a1*w4.x; acc1[4*j+1] += a1*w4.y;
                        acc1[4*j+2] += a1*w4.z; acc1[4*j+3] += a1*w4.w;
                    }
                }
        }
        #pragma unroll
        for (int oc = 0; oc < 32; oc++) {
            float sg0 = 1.f / (1.f + __expf(-acc0[oc]));
            float sg1 = 1.f / (1.f + __expf(-acc1[oc]));
            __nv_bfloat16 h0 = __float2bfloat16(sg0);
            __nv_bfloat16 h1 = __float2bfloat16(sg1);
            uint32_t ph = (uint32_t)__bfloat16_as_ushort(h0)
                        | ((uint32_t)__bfloat16_as_ushort(h1) << 16);
            uint32_t pl = (uint32_t)__bfloat16_as_ushort(__float2bfloat16(sg0 - __bfloat162float(h0)))
                        | ((uint32_t)__bfloat16_as_ushort(__float2bfloat16(sg1 - __bfloat162float(h1))) << 16);
            size_t idx = (size_t)b*32*NPIX + (size_t)oc*NPIX + p0;
            *(uint32_t*)((uint16_t*)g_ah + idx) = ph;
            *(uint32_t*)((uint16_t*)g_al + idx) = pl;
        }
    }
}

// ---------------- W split: fp32 -> bf16 hi/lo (FC weights) ----------------
__global__ void split_w_kernel(const float* __restrict__ W) {
    int i = blockIdx.x*blockDim.x + threadIdx.x;
    if (i < FC_N*FC_K) {
        float x = W[i];
        __nv_bfloat16 h = __float2bfloat16(x);
        g_wh[i] = h;
        g_wl[i] = __float2bfloat16(x - __bfloat162float(h));
    }
}

// ---------------- warp-MMA FC GEMM (portable mma.sync, bf16 3-pass) -------
#define BM 128
#define BN 96
#define NCH 54
#define GM_ITERS (3*NCH)
#define AROW 144
#define ABUF (128*AROW)
#define BBUF (96*AROW)
#define GM_SMEM (2*ABUF + 2*BBUF)

__global__ void __launch_bounds__(256, 2)
gemm_fc_mma(const float* __restrict__ bias, float* __restrict__ C) {
    extern __shared__ char sm[];
    uint32_t saA = smem_u32(sm);
    uint32_t saB = saA + 2*ABUF;

    int tid = threadIdx.x;
    int wid = tid >> 5, lane = tid & 31;
    int g = lane >> 2, q = lane & 3;
    int wm = wid >> 1;
    int wn = wid & 1;
    int block_m = blockIdx.y * BM;
    int block_n = blockIdx.x * BN;

    float acc[2][6][4] = {};

    auto issue = [&](int it, int buf) {
        int pass = it / NCH;
        int kc = it - pass*NCH;
        const char* Ab = (const char*)(pass == 2 ? g_al : g_ah)
                       + (size_t)block_m*6912 + (size_t)kc*128;
        const char* Bb = (const char*)(pass == 1 ? g_wl : g_wh)
                       + (size_t)block_n*6912 + (size_t)kc*128;
        uint32_t da = saA + buf*ABUF;
        uint32_t db = saB + buf*BBUF;
        #pragma unroll
        for (int j = 0; j < 4; j++) {
            int slot = tid + j*256;
            int r = slot >> 3, seg = slot & 7;
            uint32_t d = da + r*AROW + seg*16;
            const char* s = Ab + (size_t)r*6912 + seg*16;
            asm volatile("cp.async.cg.shared.global [%0], [%1], 16;"
                         :: "r"(d), "l"(s));
        }
        #pragma unroll
        for (int j = 0; j < 3; j++) {
            int slot = tid + j*256;
            int r = slot >> 3, seg = slot & 7;
            uint32_t d = db + r*AROW + seg*16;
            const char* s = Bb + (size_t)r*6912 + seg*16;
            asm volatile("cp.async.cg.shared.global [%0], [%1], 16;"
                         :: "r"(d), "l"(s));
        }
        asm volatile("cp.async.commit_group;" ::: "memory");
    };

    issue(0, 0);
    for (int it = 0; it < GM_ITERS; it++) {
        int cur = it & 1;
        if (it + 1 < GM_ITERS) {
            issue(it + 1, 1 - cur);
            asm volatile("cp.async.wait_group 1;" ::: "memory");
        } else {
            asm volatile("cp.async.wait_group 0;" ::: "memory");
        }
        __syncthreads();

        uint32_t ab = saA + cur*ABUF;
        uint32_t bb = saB + cur*BBUF;
        #pragma unroll
        for (int kk = 0; kk < 4; kk++) {
            uint32_t koff = kk*32 + q*4;
            uint32_t bf[6][2];
            #pragma unroll
            for (int nt = 0; nt < 6; nt++) {
                uint32_t addr = bb + (uint32_t)(wn*48 + nt*8 + g)*AROW + koff;
                LDS32(bf[nt][0], addr);
                LDS32(bf[nt][1], addr + 16);
            }
            #pragma unroll
            for (int mt = 0; mt < 2; mt++) {
                uint32_t base = ab + (uint32_t)(wm*32 + mt*16 + g)*AROW + koff;
                uint32_t a0, a1, a2, a3;
                LDS32(a0, base);
                LDS32(a2, base + 16);
                LDS32(a1, base + 8*AROW);
                LDS32(a3, base + 8*AROW + 16);
                #pragma unroll
                for (int nt = 0; nt < 6; nt++)
                    MMA16816(acc[mt][nt], a0, a1, a2, a3, bf[nt][0], bf[nt][1]);
            }
        }
        __syncthreads();
    }

    #pragma unroll
    for (int mt = 0; mt < 2; mt++) {
        int row = block_m + wm*32 + mt*16 + g;
        #pragma unroll
        for (int nt = 0; nt < 6; nt++) {
            int col = block_n + wn*48 + nt*8 + 2*q;
            float bv0 = bias[col], bv1 = bias[col+1];
            float2 v0 = make_float2(acc[mt][nt][0] + bv0, acc[mt][nt][1] + bv1);
            float2 v1 = make_float2(acc[mt][nt][2] + bv0, acc[mt][nt][3] + bv1);
            *(float2*)&C[(size_t)row*FC_N + col] = v0;
            *(float2*)&C[(size_t)(row+8)*FC_N + col] = v1;
        }
    }
}

// ---------------- fused Kuramoto: angle-sum factorization -----------------
// sin(pj-pi) = sin pj cos pi - cos pj sin pi
// Per step: phase A computes per-osc sin/cos (2 MUFU/osc, 4x fewer than
// per-edge); phase B does 2 FMA + 2 LDS per edge.
__global__ void kuramoto_all(const float* __restrict__ init,
                             float* __restrict__ out,
                             const float* __restrict__ coup,
                             const int* __restrict__ conn) {
    extern __shared__ char dynraw[];
    float* sc   = (float*)dynraw;                // [NOSC*KCON]
    int*   sj   = (int*)(sc + NOSC*KCON);        // [NOSC*KCON]
    float* ph0  = (float*)(sj + NOSC*KCON);      // [NOSC]
    float* ph1  = ph0 + NOSC;                    // [NOSC]
    float* ssin = ph1 + NOSC;                    // [NOSC]
    float* scos = ssin + NOSC;                   // [NOSC]

    int b = blockIdx.x;
    int tid = threadIdx.x;
    const float* cb = coup + (size_t)b*NOSC*KCON;
    const int*   jb = conn + (size_t)b*NOSC*KCON;

    for (int i = tid; i < NOSC*KCON; i += blockDim.x) {
        sc[i] = cb[i];
        sj[i] = jb[i];
    }
    for (int i = tid; i < NOSC; i += blockDim.x) {
        float p = init[(size_t)b*NOSC + i];
        ph0[i] = p;
        out[(size_t)b*NOSC + i] = p;
    }
    __syncthreads();

    float ep = 0.1f;
    float* cur = ph0;
    float* nxt = ph1;
    for (int s = 0; s < STEPS; s++) {
        for (int i = tid; i < NOSC; i += blockDim.x) {
            float p = cur[i];
            ssin[i] = __sinf(p);
            scos[i] = __cosf(p);
        }
        __syncthreads();
        float* dst = out + (size_t)(s+1)*PHASE_SLICE + (size_t)b*NOSC;
        for (int i = tid; i < NOSC; i += blockDim.x) {
            float p = cur[i];
            float si = ssin[i], ci = scos[i];
            float as = 0.f, ac = 0.f;
            #pragma unroll
            for (int k = 0; k < KCON; k++) {
                int   j = sj[i*KCON + k];
                float c = sc[i*KCON + k];
                as += c * ssin[j];
                ac += c * scos[j];
            }
            float np = p + ep*(ci*as - si*ac);
            nxt[i] = np;
            dst[i] = np;
        }
        ep = ep - (0.5f*(float)s)*ep/25.0f;
        float* t = cur; cur = nxt; nxt = t;
        __syncthreads();
    }
}

// ---------------- launch ----------------
extern "C" void kernel_launch(void* const* d_in, const int* in_sizes, int n_in,
                              void* d_out, int out_size) {
    const float* input      = (const float*)d_in[0];
    const float* init_phase = (const float*)d_in[1];
    const int*   conn       = (const int*)  d_in[2];
    const float* w1 = (const float*)d_in[4];
    const float* b1 = (const float*)d_in[5];
    const float* w2 = (const float*)d_in[6];
    const float* b2 = (const float*)d_in[7];
    const float* w3 = (const float*)d_in[8];
    const float* b3 = (const float*)d_in[9];
    const float* fw = (const float*)d_in[10];
    const float* fb = (const float*)d_in[11];

    float* out   = (float*)d_out;
    float* fcout = out + PHASE_TOTAL;

    conv1_kernel<<<BATCH, 256>>>(input, w1, b1);

    split_w_kernel<<<(FC_N*FC_K + 255)/256, 256>>>(fw);

    conv2_kernel<<<BATCH, 512>>>(w2, b2);

    int c3_smem = (16*NPIX + 16*9*32 + 32) * (int)sizeof(float);
    cudaFuncSetAttribute(conv3_kernel, cudaFuncAttributeMaxDynamicSharedMemorySize, c3_smem);
    conv3_kernel<<<BATCH, 512, c3_smem>>>(w3, b3);

    cudaFuncSetAttribute(gemm_fc_mma, cudaFuncAttributeMaxDynamicSharedMemorySize, GM_SMEM);
    dim3 ggrid(FC_N/BN, FC_M/BM);
    gemm_fc_mma<<<ggrid, 256, GM_SMEM>>>(fb, fcout);

    int ksmem = (NOSC*KCON)*(int)(sizeof(float) + sizeof(int))
              + 4*NOSC*(int)sizeof(float);
    cudaFuncSetAttribute(kuramoto_all, cudaFuncAttributeMaxDynamicSharedMemorySize, ksmem);
    kuramoto_all<<<BATCH, 512, ksmem>>>(init_phase, out, fcout, conn);
}

// round 17
// speedup vs baseline: 1.1243x; 1.1243x over previous
#include <cuda_runtime.h>
#include <cuda_bf16.h>
#include <math.h>
#include <stdint.h>

#define BATCH 512
#define HW 36
#define NPIX 1296
#define NOSC 1296
#define KCON 8
#define STEPS 25

#define FC_M 6144
#define FC_K 3456
#define FC_N 864

#define PHASE_SLICE (BATCH*NOSC)
#define PHASE_TOTAL ((STEPS+1)*PHASE_SLICE)

// ---------------- scratch ----------------
__device__ float g_c1[BATCH*8*NPIX];
__device__ float g_c2[BATCH*16*NPIX];
__device__ __nv_bfloat16 g_ah[(size_t)FC_M*FC_K];
__device__ __nv_bfloat16 g_al[(size_t)FC_M*FC_K];
__device__ __nv_bfloat16 g_wh[(size_t)FC_N*FC_K];
__device__ __nv_bfloat16 g_wl[(size_t)FC_N*FC_K];

__device__ __forceinline__ uint32_t smem_u32(const void* p) {
    uint32_t a;
    asm("{ .reg .u64 t; cvta.to.shared.u64 t, %1; cvt.u32.u64 %0, t; }"
        : "=r"(a) : "l"(p));
    return a;
}
#define LDS32(v, addr) \
    asm volatile("ld.shared.b32 %0, [%1];" : "=r"(v) : "r"(addr))
#define MMA16816(d, a0,a1,a2,a3, b0,b1) \
    asm volatile("mma.sync.aligned.m16n8k16.row.col.f32.bf16.bf16.f32 " \
        "{%0,%1,%2,%3}, {%4,%5,%6,%7}, {%8,%9}, {%0,%1,%2,%3};" \
        : "+f"((d)[0]),"+f"((d)[1]),"+f"((d)[2]),"+f"((d)[3]) \
        : "r"(a0),"r"(a1),"r"(a2),"r"(a3),"r"(b0),"r"(b1))

// ---------------- conv1: 1 -> 8, relu ----------------
__global__ void conv1_kernel(const float* __restrict__ in,
                             const float* __restrict__ w,
                             const float* __restrict__ bias) {
    __shared__ float s[NPIX];
    int b = blockIdx.x;
    for (int i = threadIdx.x; i < NPIX; i += blockDim.x) s[i] = in[b*NPIX + i];
    __syncthreads();
    for (int idx = threadIdx.x; idx < 8*NPIX; idx += blockDim.x) {
        int oc = idx / NPIX, p = idx - oc*NPIX;
        int h = p / HW, x = p - h*HW;
        float acc = bias[oc];
        #pragma unroll
        for (int kh = 0; kh < 3; kh++) {
            int ih = h + kh - 1;
            if ((unsigned)ih >= HW) continue;
            #pragma unroll
            for (int kw = 0; kw < 3; kw++) {
                int iw = x + kw - 1;
                if ((unsigned)iw >= HW) continue;
                acc += s[ih*HW + iw] * w[oc*9 + kh*3 + kw];
            }
        }
        g_c1[b*8*NPIX + idx] = fmaxf(acc, 0.f);
    }
}

// ---------------- conv2: 8 -> 16, relu; 2-pixel tiling (R11 config) -------
__global__ void __launch_bounds__(512)
conv2_kernel(const float* __restrict__ w,
             const float* __restrict__ bias) {
    __shared__ float s[8*NPIX];
    __shared__ float ws[8*9*16];     // [ic][k][oc]
    __shared__ float bs[16];
    int b = blockIdx.x;
    for (int i = threadIdx.x; i < 8*NPIX; i += blockDim.x) s[i] = g_c1[b*8*NPIX + i];
    for (int i = threadIdx.x; i < 16*8*9; i += blockDim.x) {
        int oc = i / 72, r = i - oc*72;
        ws[r*16 + oc] = w[i];
    }
    if (threadIdx.x < 16) bs[threadIdx.x] = bias[threadIdx.x];
    __syncthreads();
    for (int t = threadIdx.x; t < NPIX/2; t += blockDim.x) {
        int p0 = 2*t;
        int h = p0 / HW, x0 = p0 - h*HW;
        float acc0[16], acc1[16];
        #pragma unroll
        for (int oc = 0; oc < 16; oc++) { acc0[oc] = bs[oc]; acc1[oc] = bs[oc]; }
        for (int ic = 0; ic < 8; ic++) {
            float v[3][4];
            #pragma unroll
            for (int kh = 0; kh < 3; kh++) {
                int r = h + kh - 1;
                bool rok = (unsigned)r < HW;
                #pragma unroll
                for (int j = 0; j < 4; j++) {
                    int c = x0 + j - 1;
                    v[kh][j] = (rok && (unsigned)c < HW) ? s[ic*NPIX + r*HW + c] : 0.f;
                }
            }
            #pragma unroll
            for (int kh = 0; kh < 3; kh++)
                #pragma unroll
                for (int kw = 0; kw < 3; kw++) {
                    float a0 = v[kh][kw], a1 = v[kh][kw+1];
                    const float4* wp = (const float4*)&ws[((ic*3+kh)*3+kw)*16];
                    #pragma unroll
                    for (int j = 0; j < 4; j++) {
                        float4 w4 = wp[j];
                        acc0[4*j+0] += a0*w4.x; acc0[4*j+1] += a0*w4.y;
                        acc0[4*j+2] += a0*w4.z; acc0[4*j+3] += a0*w4.w;
                        acc1[4*j+0] += a1*w4.x; acc1[4*j+1] += a1*w4.y;
                        acc1[4*j+2] += a1*w4.z; acc1[4*j+3] += a1*w4.w;
                    }
                }
        }
        #pragma unroll
        for (int oc = 0; oc < 16; oc++) {
            float2 o = make_float2(fmaxf(acc0[oc], 0.f), fmaxf(acc1[oc], 0.f));
            *(float2*)&g_c2[(size_t)b*16*NPIX + (size_t)oc*NPIX + p0] = o;
        }
    }
}

// ---------------- conv3: 16 -> 32, sigmoid; 2-pixel tiling (R11 config) ---
__global__ void __launch_bounds__(512)
conv3_kernel(const float* __restrict__ w,
             const float* __restrict__ bias) {
    extern __shared__ float dyn[];
    float* s  = dyn;                  // 16*NPIX
    float* ws = dyn + 16*NPIX;        // [ic][k][oc] 16*9*32
    float* bs = ws + 16*9*32;         // 32
    int b = blockIdx.x;
    for (int i = threadIdx.x; i < 16*NPIX; i += blockDim.x) s[i] = g_c2[b*16*NPIX + i];
    for (int i = threadIdx.x; i < 32*16*9; i += blockDim.x) {
        int oc = i / 144, r = i - oc*144;
        ws[r*32 + oc] = w[i];
    }
    if (threadIdx.x < 32) bs[threadIdx.x] = bias[threadIdx.x];
    __syncthreads();
    for (int t = threadIdx.x; t < NPIX/2; t += blockDim.x) {
        int p0 = 2*t;
        int h = p0 / HW, x0 = p0 - h*HW;
        float acc0[32], acc1[32];
        #pragma unroll
        for (int oc = 0; oc < 32; oc++) { acc0[oc] = bs[oc]; acc1[oc] = bs[oc]; }
        for (int ic = 0; ic < 16; ic++) {
            float v[3][4];
            #pragma unroll
            for (int kh = 0; kh < 3; kh++) {
                int r = h + kh - 1;
                bool rok = (unsigned)r < HW;
                #pragma unroll
                for (int j = 0; j < 4; j++) {
                    int c = x0 + j - 1;
                    v[kh][j] = (rok && (unsigned)c < HW) ? s[ic*NPIX + r*HW + c] : 0.f;
                }
            }
            #pragma unroll
            for (int kh = 0; kh < 3; kh++)
                #pragma unroll
                for (int kw = 0; kw < 3; kw++) {
                    float a0 = v[kh][kw], a1 = v[kh][kw+1];
                    const float4* wp = (const float4*)&ws[((ic*3+kh)*3+kw)*32];
                    #pragma unroll
                    for (int j = 0; j < 8; j++) {
                        float4 w4 = wp[j];
                        acc0[4*j+0] += a0*w4.x; acc0[4*j+1] += a0*w4.y;
                        acc0[4*j+2] += a0*w4.z; acc0[4*j+3] += a0*w4.w;
                        acc1[4*j+0] += a1*w4.x; acc1[4*j+1] += a1*w4.y;
                        acc1[4*j+2] += a1*w4.z; acc1[4*j+3] += a1*w4.w;
                    }
                }
        }
        #pragma unroll
        for (int oc = 0; oc < 32; oc++) {
            float sg0 = 1.f / (1.f + __expf(-acc0[oc]));
            float sg1 = 1.f / (1.f + __expf(-acc1[oc]));
            __nv_bfloat16 h0 = __float2bfloat16(sg0);
            __nv_bfloat16 h1 = __float2bfloat16(sg1);
            uint32_t ph = (uint32_t)__bfloat16_as_ushort(h0)
                        | ((uint32_t)__bfloat16_as_ushort(h1) << 16);
            uint32_t pl = (uint32_t)__bfloat16_as_ushort(__float2bfloat16(sg0 - __bfloat162float(h0)))
                        | ((uint32_t)__bfloat16_as_ushort(__float2bfloat16(sg1 - __bfloat162float(h1))) << 16);
            size_t idx = (size_t)b*32*NPIX + (size_t)oc*NPIX + p0;
            *(uint32_t*)((uint16_t*)g_ah + idx) = ph;
            *(uint32_t*)((uint16_t*)g_al + idx) = pl;
        }
    }
}

// ---------------- W split: fp32 -> bf16 hi/lo (FC weights) ----------------
__global__ void split_w_kernel(const float* __restrict__ W) {
    int i = blockIdx.x*blockDim.x + threadIdx.x;
    if (i < FC_N*FC_K) {
        float x = W[i];
        __nv_bfloat16 h = __float2bfloat16(x);
        g_wh[i] = h;
        g_wl[i] = __float2bfloat16(x - __bfloat162float(h));
    }
}

// ---------------- warp-MMA FC GEMM (portable mma.sync, bf16 3-pass) -------
// BM=192: grid = 32x9 = 288 CTAs = ~1.0 wave at 2 CTAs/SM (was 432 = 1.46)
#define BM 192
#define BN 96
#define NCH 54
#define GM_ITERS (3*NCH)
#define AROW 144
#define ABUF (BM*AROW)       // 27648
#define BBUF (96*AROW)       // 13824
#define GM_SMEM (2*ABUF + 2*BBUF)   // 82944

__global__ void __launch_bounds__(256, 2)
gemm_fc_mma(const float* __restrict__ bias, float* __restrict__ C) {
    extern __shared__ char sm[];
    uint32_t saA = smem_u32(sm);
    uint32_t saB = saA + 2*ABUF;

    int tid = threadIdx.x;
    int wid = tid >> 5, lane = tid & 31;
    int g = lane >> 2, q = lane & 3;
    int wm = wid >> 1;          // 0..3 -> 48 rows each
    int wn = wid & 1;           // 0..1 -> 48 cols each
    int block_m = blockIdx.y * BM;
    int block_n = blockIdx.x * BN;

    float acc[3][6][4] = {};

    auto issue = [&](int it, int buf) {
        int pass = it / NCH;
        int kc = it - pass*NCH;
        const char* Ab = (const char*)(pass == 2 ? g_al : g_ah)
                       + (size_t)block_m*6912 + (size_t)kc*128;
        const char* Bb = (const char*)(pass == 1 ? g_wl : g_wh)
                       + (size_t)block_n*6912 + (size_t)kc*128;
        uint32_t da = saA + buf*ABUF;
        uint32_t db = saB + buf*BBUF;
        #pragma unroll
        for (int j = 0; j < 6; j++) {          // 192 rows * 8 segs / 256
            int slot = tid + j*256;
            int r = slot >> 3, seg = slot & 7;
            uint32_t d = da + r*AROW + seg*16;
            const char* s = Ab + (size_t)r*6912 + seg*16;
            asm volatile("cp.async.cg.shared.global [%0], [%1], 16;"
                         :: "r"(d), "l"(s));
        }
        #pragma unroll
        for (int j = 0; j < 3; j++) {          // 96 rows * 8 segs / 256
            int slot = tid + j*256;
            int r = slot >> 3, seg = slot & 7;
            uint32_t d = db + r*AROW + seg*16;
            const char* s = Bb + (size_t)r*6912 + seg*16;
            asm volatile("cp.async.cg.shared.global [%0], [%1], 16;"
                         :: "r"(d), "l"(s));
        }
        asm volatile("cp.async.commit_group;" ::: "memory");
    };

    issue(0, 0);
    for (int it = 0; it < GM_ITERS; it++) {
        int cur = it & 1;
        if (it + 1 < GM_ITERS) {
            issue(it + 1, 1 - cur);
            asm volatile("cp.async.wait_group 1;" ::: "memory");
        } else {
            asm volatile("cp.async.wait_group 0;" ::: "memory");
        }
        __syncthreads();

        uint32_t ab = saA + cur*ABUF;
        uint32_t bb = saB + cur*BBUF;
        #pragma unroll
        for (int kk = 0; kk < 4; kk++) {
            uint32_t koff = kk*32 + q*4;
            uint32_t bf[6][2];
            #pragma unroll
            for (int nt = 0; nt < 6; nt++) {
                uint32_t addr = bb + (uint32_t)(wn*48 + nt*8 + g)*AROW + koff;
                LDS32(bf[nt][0], addr);
                LDS32(bf[nt][1], addr + 16);
            }
            #pragma unroll
            for (int mt = 0; mt < 3; mt++) {
                uint32_t base = ab + (uint32_t)(wm*48 + mt*16 + g)*AROW + koff;
                uint32_t a0, a1, a2, a3;
                LDS32(a0, base);
                LDS32(a2, base + 16);
                LDS32(a1, base + 8*AROW);
                LDS32(a3, base + 8*AROW + 16);
                #pragma unroll
                for (int nt = 0; nt < 6; nt++)
                    MMA16816(acc[mt][nt], a0, a1, a2, a3, bf[nt][0], bf[nt][1]);
            }
        }
        __syncthreads();
    }

    #pragma unroll
    for (int mt = 0; mt < 3; mt++) {
        int row = block_m + wm*48 + mt*16 + g;
        #pragma unroll
        for (int nt = 0; nt < 6; nt++) {
            int col = block_n + wn*48 + nt*8 + 2*q;
            float bv0 = bias[col], bv1 = bias[col+1];
            float2 v0 = make_float2(acc[mt][nt][0] + bv0, acc[mt][nt][1] + bv1);
            float2 v1 = make_float2(acc[mt][nt][2] + bv0, acc[mt][nt][3] + bv1);
            *(float2*)&C[(size_t)row*FC_N + col] = v0;
            *(float2*)&C[(size_t)(row+8)*FC_N + col] = v1;
        }
    }
}

// ---------------- fused Kuramoto (R11 direct __sinf) ----------------
__global__ void kuramoto_all(const float* __restrict__ init,
                             float* __restrict__ out,
                             const float* __restrict__ coup,
                             const int* __restrict__ conn) {
    extern __shared__ char dynraw[];
    float* sc  = (float*)dynraw;
    int*   sj  = (int*)(sc + NOSC*KCON);
    float* ph0 = (float*)(sj + NOSC*KCON);
    float* ph1 = ph0 + NOSC;

    int b = blockIdx.x;
    int tid = threadIdx.x;
    const float* cb = coup + (size_t)b*NOSC*KCON;
    const int*   jb = conn + (size_t)b*NOSC*KCON;

    for (int i = tid; i < NOSC*KCON; i += blockDim.x) {
        sc[i] = cb[i];
        sj[i] = jb[i];
    }
    for (int i = tid; i < NOSC; i += blockDim.x) {
        float p = init[(size_t)b*NOSC + i];
        ph0[i] = p;
        out[(size_t)b*NOSC + i] = p;
    }
    __syncthreads();

    float ep = 0.1f;
    float* cur = ph0;
    float* nxt = ph1;
    for (int s = 0; s < STEPS; s++) {
        float* dst = out + (size_t)(s+1)*PHASE_SLICE + (size_t)b*NOSC;
        for (int i = tid; i < NOSC; i += blockDim.x) {
            float p = cur[i];
            float acc = 0.f;
            #pragma unroll
            for (int k = 0; k < KCON; k++) {
                acc += sc[i*KCON + k] * __sinf(cur[sj[i*KCON + k]] - p);
            }
            float np = p + ep*acc;
            nxt[i] = np;
            dst[i] = np;
        }
        ep = ep - (0.5f*(float)s)*ep/25.0f;
        float* t = cur; cur = nxt; nxt = t;
        __syncthreads();
    }
}

// ---------------- launch ----------------
extern "C" void kernel_launch(void* const* d_in, const int* in_sizes, int n_in,
                              void* d_out, int out_size) {
    const float* input      = (const float*)d_in[0];
    const float* init_phase = (const float*)d_in[1];
    const int*   conn       = (const int*)  d_in[2];
    const float* w1 = (const float*)d_in[4];
    const float* b1 = (const float*)d_in[5];
    const float* w2 = (const float*)d_in[6];
    const float* b2 = (const float*)d_in[7];
    const float* w3 = (const float*)d_in[8];
    const float* b3 = (const float*)d_in[9];
    const float* fw = (const float*)d_in[10];
    const float* fb = (const float*)d_in[11];

    float* out   = (float*)d_out;
    float* fcout = out + PHASE_TOTAL;

    conv1_kernel<<<BATCH, 256>>>(input, w1, b1);

    split_w_kernel<<<(FC_N*FC_K + 255)/256, 256>>>(fw);

    conv2_kernel<<<BATCH, 512>>>(w2, b2);

    int c3_smem = (16*NPIX + 16*9*32 + 32) * (int)sizeof(float);
    cudaFuncSetAttribute(conv3_kernel, cudaFuncAttributeMaxDynamicSharedMemorySize, c3_smem);
    conv3_kernel<<<BATCH, 512, c3_smem>>>(w3, b3);

    cudaFuncSetAttribute(gemm_fc_mma, cudaFuncAttributeMaxDynamicSharedMemorySize, GM_SMEM);
    dim3 ggrid(FC_N/BN, FC_M/BM);   // (9, 32) = 288 CTAs
    gemm_fc_mma<<<ggrid, 256, GM_SMEM>>>(fb, fcout);

    int ksmem = (NOSC*KCON)*(int)(sizeof(float) + sizeof(int))
              + 2*NOSC*(int)sizeof(float);
    cudaFuncSetAttribute(kuramoto_all, cudaFuncAttributeMaxDynamicSharedMemorySize, ksmem);
    kuramoto_all<<<BATCH, 512, ksmem>>>(init_phase, out, fcout, conn);
}